// round 1
// baseline (speedup 1.0000x reference)
#include <cuda_runtime.h>
#include <math_constants.h>

#define IMG    256
#define DET    362          // int(256*sqrt(2)+0.5)
#define A_FULL 177          // (45-1)*4 + 1
#define N_ACQ  45
#define NB     2

// Scratch (allocation-free): sinogram after data-consistency, and filtered sinogram.
__device__ float g_sino[NB * A_FULL * DET];
__device__ float g_sf  [NB * A_FULL * DET];

// ---------------------------------------------------------------------------
// Kernel 1: Radon transform + data-consistency substitution.
// grid = (A_FULL, NB), block = 384 (362 active threads, one per detector bin t)
// sino[b][a][t] = sum_S bilinear(img, xs, ys);  at acquired angles (a%4==0):
// sino = s_target[b][t][a/4] - sino.
// ---------------------------------------------------------------------------
__global__ void radon_dc_kernel(const float* __restrict__ img,
                                const float* __restrict__ s_target,
                                const float* __restrict__ thetas_deg)
{
    const int a = blockIdx.x;
    const int b = blockIdx.y;
    const int t = threadIdx.x;

    const float th = thetas_deg[a] * (float)(CUDART_PI / 180.0);
    const float c = cosf(th);
    const float s = sinf(th);

    if (t >= DET) return;

    const float* __restrict__ im = img + b * IMG * IMG;

    const float T  = (float)t - (float)(DET - 1) * 0.5f;
    const float bx = T * c + 127.5f;   // (W-1)/2
    const float by = T * s + 127.5f;   // (H-1)/2

    float acc = 0.f;

    #pragma unroll 2
    for (int k = 0; k < DET; k++) {
        const float S  = (float)k - (float)(DET - 1) * 0.5f;
        const float xs = bx - S * s;
        const float ys = by + S * c;

        // If all four corners are invalid / all weights to valid corners are 0,
        // the sample contributes nothing.
        if (xs <= -1.f || xs >= 256.f || ys <= -1.f || ys >= 256.f) continue;

        const float x0f = floorf(xs), y0f = floorf(ys);
        const float wx = xs - x0f,    wy = ys - y0f;
        const int   x0 = (int)x0f,    y0 = (int)y0f;

        float v00, v01, v10, v11;
        if ((unsigned)x0 < 255u && (unsigned)y0 < 255u) {
            // fast interior path: all 4 corners valid
            const float* p = im + y0 * IMG + x0;
            v00 = __ldg(p);
            v01 = __ldg(p + 1);
            v10 = __ldg(p + IMG);
            v11 = __ldg(p + IMG + 1);
        } else {
            const bool xv0 = ((unsigned)x0       < 256u);
            const bool xv1 = ((unsigned)(x0 + 1) < 256u);
            const bool yv0 = ((unsigned)y0       < 256u);
            const bool yv1 = ((unsigned)(y0 + 1) < 256u);
            v00 = (xv0 && yv0) ? __ldg(im + y0 * IMG + x0)             : 0.f;
            v01 = (xv1 && yv0) ? __ldg(im + y0 * IMG + x0 + 1)         : 0.f;
            v10 = (xv0 && yv1) ? __ldg(im + (y0 + 1) * IMG + x0)       : 0.f;
            v11 = (xv1 && yv1) ? __ldg(im + (y0 + 1) * IMG + x0 + 1)   : 0.f;
        }
        const float top = v00 + wx * (v01 - v00);
        const float bot = v10 + wx * (v11 - v10);
        acc += top + wy * (bot - top);
    }

    // Data consistency: acquired angles are a = 0,4,...,176 (acq_idx = j*4)
    if ((a & 3) == 0) {
        const int j = a >> 2;
        const float tgt = __ldg(s_target + (b * DET + t) * N_ACQ + j);
        acc = tgt - acc;
    }

    g_sino[(b * A_FULL + a) * DET + t] = acc;
}

// ---------------------------------------------------------------------------
// Kernel 2: Ramp filter as exact direct convolution.
// The reference's FFT filtering (pad=1024) with filt = FFT(2f), f real-symmetric,
// reduces EXACTLY to sf[d] = sum_k sino[k] * h[|d-k|] with
//   h[0] = 0.5,  h[m odd] = -2/(pi*m)^2,  h[m even>0] = 0.
// grid = (A_FULL, NB), block = 384.
// ---------------------------------------------------------------------------
__global__ void filter_kernel()
{
    __shared__ float xcol[DET];
    __shared__ float wtab[DET];

    const int a = blockIdx.x;
    const int b = blockIdx.y;
    const int d = threadIdx.x;

    const float* __restrict__ col = g_sino + (b * A_FULL + a) * DET;
    for (int i = threadIdx.x; i < DET; i += blockDim.x) {
        xcol[i] = col[i];
        float wm;
        if (i == 0)      wm = 0.5f;
        else if (i & 1)  { const float fm = (float)i * (float)CUDART_PI; wm = -2.0f / (fm * fm); }
        else             wm = 0.f;
        wtab[i] = wm;
    }
    __syncthreads();

    if (d >= DET) return;

    float acc = 0.5f * xcol[d];
    const int k0 = (d & 1) ^ 1;           // opposite parity -> |d-k| odd
    #pragma unroll 4
    for (int k = k0; k < DET; k += 2) {
        const int m = abs(d - k);
        acc += wtab[m] * xcol[k];
    }
    g_sf[(b * A_FULL + a) * DET + d] = acc;
}

// ---------------------------------------------------------------------------
// Kernel 3: Filtered backprojection.
// One thread per output pixel; loop over 177 angles with cos/sin in smem.
// t = cos*gx + sin*gy + 180.5 is always in (0.18, 360.83) -> interp in-range.
// grid = 512, block = 256.
// ---------------------------------------------------------------------------
__global__ void bp_kernel(float* __restrict__ out,
                          const float* __restrict__ thetas_deg)
{
    __shared__ float cs[A_FULL];
    __shared__ float sn[A_FULL];

    if (threadIdx.x < A_FULL) {
        const float th = thetas_deg[threadIdx.x] * (float)(CUDART_PI / 180.0);
        cs[threadIdx.x] = cosf(th);
        sn[threadIdx.x] = sinf(th);
    }
    __syncthreads();

    const int p   = blockIdx.x * blockDim.x + threadIdx.x;   // 0 .. 131071
    const int b   = p >> 16;
    const int pix = p & 65535;
    const int y   = pix >> 8;
    const int x   = pix & 255;

    const float gx = (float)x - 127.5f;
    const float gy = (float)y - 127.5f;

    const float* __restrict__ sfb = g_sf + b * A_FULL * DET;

    float acc = 0.f;
    #pragma unroll 3
    for (int a = 0; a < A_FULL; a++) {
        const float t  = cs[a] * gx + sn[a] * gy + (float)(DET - 1) * 0.5f;
        const float t0 = floorf(t);
        const float w  = t - t0;
        int i = (int)t0;
        i = min(max(i, 0), DET - 2);            // never triggered; safety clamp
        const float* row = sfb + a * DET;
        const float v0 = __ldg(row + i);
        const float v1 = __ldg(row + i + 1);
        acc += v0 + w * (v1 - v0);
    }
    out[p] = acc * (float)(CUDART_PI / (2.0 * A_FULL));
}

// ---------------------------------------------------------------------------
extern "C" void kernel_launch(void* const* d_in, const int* in_sizes, int n_in,
                              void* d_out, int out_size)
{
    // Defensive input mapping by element count (all counts distinct):
    //   x_source  : 2*1*256*256 = 131072
    //   s_target  : 2*1*362*45  = 32580
    //   thetas_deg: 177
    //   acq_idx   : 45 (pattern hard-coded: arange(45)*4)
    const float* x_source = nullptr;
    const float* s_target = nullptr;
    const float* thetas   = nullptr;
    for (int i = 0; i < n_in; i++) {
        if      (in_sizes[i] == NB * IMG * IMG)   x_source = (const float*)d_in[i];
        else if (in_sizes[i] == NB * DET * N_ACQ) s_target = (const float*)d_in[i];
        else if (in_sizes[i] == A_FULL)           thetas   = (const float*)d_in[i];
    }

    dim3 grid_as(A_FULL, NB);
    radon_dc_kernel<<<grid_as, 384>>>(x_source, s_target, thetas);
    filter_kernel  <<<grid_as, 384>>>();
    bp_kernel      <<<512, 256>>>((float*)d_out, thetas);
}

// round 2
// speedup vs baseline: 1.9827x; 1.9827x over previous
#include <cuda_runtime.h>
#include <math_constants.h>

#define IMG    256
#define DET    362          // int(256*sqrt(2)+0.5)
#define A_FULL 177          // (45-1)*4 + 1
#define N_ACQ  45
#define NB     2
#define NCHUNK 4
#define CHSZ   ((DET + NCHUNK - 1) / NCHUNK)   // 91

// Scratch (allocation-free)
__device__ float g_part[NCHUNK * NB * A_FULL * DET];  // radon partial sums
__device__ float g_sf  [NB * A_FULL * DET];           // filtered sinogram
__device__ float g_imT [NB * IMG * IMG];              // transposed image

// ---------------------------------------------------------------------------
// Kernel 0: image transpose (for steep-angle coalescing).
// ---------------------------------------------------------------------------
__global__ void transpose_kernel(const float* __restrict__ img)
{
    __shared__ float tile[32][33];
    const int b  = blockIdx.z;
    const int x0 = blockIdx.x * 32;
    const int y0 = blockIdx.y * 32;
    const int tx = threadIdx.x, ty = threadIdx.y;      // block (32, 8)

    const float* src = img  + b * IMG * IMG;
    float*       dst = g_imT + b * IMG * IMG;

    #pragma unroll
    for (int dy = 0; dy < 32; dy += 8)
        tile[ty + dy][tx] = src[(y0 + ty + dy) * IMG + x0 + tx];
    __syncthreads();
    #pragma unroll
    for (int dy = 0; dy < 32; dy += 8)
        dst[(x0 + ty + dy) * IMG + y0 + tx] = tile[tx][ty + dy];
}

// ---------------------------------------------------------------------------
// Kernel 1: Radon transform, chunked over S.
// grid = (A_FULL, NB, NCHUNK), block = 384 (one thread per detector bin t).
// For steep angles (sin > |cos|) we sample the transposed image with swapped
// coordinates (exactly equivalent) so the lane-varying coordinate is the
// contiguous memory axis.
// Valid S-interval computed in closed form; loop only over it.
// ---------------------------------------------------------------------------
__global__ void radon_kernel(const float* __restrict__ img,
                             const float* __restrict__ thetas_deg)
{
    const int a  = blockIdx.x;
    const int b  = blockIdx.y;
    const int ch = blockIdx.z;
    const int t  = threadIdx.x;
    if (t >= DET) return;

    const float th = thetas_deg[a] * (float)(CUDART_PI / 180.0);
    const float c  = cosf(th);
    const float s  = sinf(th);

    const float T  = (float)t - (float)(DET - 1) * 0.5f;
    const float bx = T * c + 127.5f;
    const float by = T * s + 127.5f;

    // swapped frame if sin dominates: (q,r) = (ys, xs) on transposed image,
    // else (q,r) = (xs, ys) on original.  q is the fast (contiguous) axis.
    const bool swp = (s > fabsf(c));
    float q0, r0, dq, dr;
    const float* imc;
    if (swp) { q0 = by; r0 = bx; dq =  c; dr = -s; imc = g_imT + b * IMG * IMG; }
    else     { q0 = bx; r0 = by; dq = -s; dr =  c; imc = img   + b * IMG * IMG; }

    // Valid S interval: q0+S*dq in (-1,256) and r0+S*dr in (-1,256)
    float Slo = -1e9f, Shi = 1e9f;
    {
        // q constraint
        if (dq > 1e-6f)       { Slo = fmaxf(Slo, (-1.f - q0) / dq); Shi = fminf(Shi, (256.f - q0) / dq); }
        else if (dq < -1e-6f) { Slo = fmaxf(Slo, (256.f - q0) / dq); Shi = fminf(Shi, (-1.f - q0) / dq); }
        else if (q0 <= -1.f || q0 >= 256.f) Shi = -2e9f;
        // r constraint
        if (dr > 1e-6f)       { Slo = fmaxf(Slo, (-1.f - r0) / dr); Shi = fminf(Shi, (256.f - r0) / dr); }
        else if (dr < -1e-6f) { Slo = fmaxf(Slo, (256.f - r0) / dr); Shi = fminf(Shi, (-1.f - r0) / dr); }
        else if (r0 <= -1.f || r0 >= 256.f) Shi = -2e9f;
    }

    const float HALF = (float)(DET - 1) * 0.5f;   // 180.5
    int klo = (int)floorf(Slo + HALF) - 1;        // padded for fp safety
    int khi = (int)ceilf (Shi + HALF) + 2;        // exclusive
    klo = max(klo, ch * CHSZ);
    khi = min(khi, min(DET, (ch + 1) * CHSZ));

    float acc = 0.f;
    #pragma unroll 2
    for (int k = klo; k < khi; k++) {
        const float S  = (float)k - HALF;
        const float qs = q0 + S * dq;
        const float rs = r0 + S * dr;
        if (qs <= -1.f || qs >= 256.f || rs <= -1.f || rs >= 256.f) continue;

        const float qf = floorf(qs), rf = floorf(rs);
        const float wq = qs - qf,    wr = rs - rf;
        const int   qi = (int)qf,    ri = (int)rf;

        float v00, v01, v10, v11;
        if ((unsigned)qi < 255u && (unsigned)ri < 255u) {
            const float* p = imc + ri * IMG + qi;
            v00 = __ldg(p);
            v01 = __ldg(p + 1);
            v10 = __ldg(p + IMG);
            v11 = __ldg(p + IMG + 1);
        } else {
            const bool qv0 = ((unsigned)qi       < 256u);
            const bool qv1 = ((unsigned)(qi + 1) < 256u);
            const bool rv0 = ((unsigned)ri       < 256u);
            const bool rv1 = ((unsigned)(ri + 1) < 256u);
            v00 = (qv0 && rv0) ? __ldg(imc + ri * IMG + qi)           : 0.f;
            v01 = (qv1 && rv0) ? __ldg(imc + ri * IMG + qi + 1)       : 0.f;
            v10 = (qv0 && rv1) ? __ldg(imc + (ri + 1) * IMG + qi)     : 0.f;
            v11 = (qv1 && rv1) ? __ldg(imc + (ri + 1) * IMG + qi + 1) : 0.f;
        }
        const float top = v00 + wq * (v01 - v00);
        const float bot = v10 + wq * (v11 - v10);
        acc += top + wr * (bot - top);
    }

    g_part[((ch * NB + b) * A_FULL + a) * DET + t] = acc;
}

// ---------------------------------------------------------------------------
// Kernel 2: combine partials + data-consistency + exact ramp-filter conv.
//   h[0]=0.5, h[m odd]=-2/(pi m)^2, h[m even>0]=0  (exactly the FFT filter)
// grid = (A_FULL, NB), block = 384.
// ---------------------------------------------------------------------------
__global__ void filter_kernel(const float* __restrict__ s_target)
{
    __shared__ float xcol[DET];
    __shared__ float wtab[DET];

    const int a = blockIdx.x;
    const int b = blockIdx.y;
    const int d = threadIdx.x;

    for (int i = threadIdx.x; i < DET; i += blockDim.x) {
        float x = 0.f;
        #pragma unroll
        for (int ci = 0; ci < NCHUNK; ci++)
            x += g_part[((ci * NB + b) * A_FULL + a) * DET + i];
        if ((a & 3) == 0) {
            const int j = a >> 2;
            x = __ldg(s_target + (b * DET + i) * N_ACQ + j) - x;
        }
        xcol[i] = x;

        float wm;
        if (i == 0)      wm = 0.5f;
        else if (i & 1)  { const float fm = (float)i * (float)CUDART_PI; wm = -2.0f / (fm * fm); }
        else             wm = 0.f;
        wtab[i] = wm;
    }
    __syncthreads();

    if (d >= DET) return;

    float acc = 0.5f * xcol[d];
    const int k0 = (d & 1) ^ 1;           // opposite parity -> |d-k| odd
    #pragma unroll 4
    for (int k = k0; k < DET; k += 2) {
        const int m = abs(d - k);
        acc += wtab[m] * xcol[k];
    }
    g_sf[(b * A_FULL + a) * DET + d] = acc;
}

// ---------------------------------------------------------------------------
// Kernel 3: Filtered backprojection. One thread per output pixel.
// ---------------------------------------------------------------------------
__global__ void bp_kernel(float* __restrict__ out,
                          const float* __restrict__ thetas_deg)
{
    __shared__ float cs[A_FULL];
    __shared__ float sn[A_FULL];

    if (threadIdx.x < A_FULL) {
        const float th = thetas_deg[threadIdx.x] * (float)(CUDART_PI / 180.0);
        cs[threadIdx.x] = cosf(th);
        sn[threadIdx.x] = sinf(th);
    }
    __syncthreads();

    const int p   = blockIdx.x * blockDim.x + threadIdx.x;   // 0 .. 131071
    const int b   = p >> 16;
    const int pix = p & 65535;
    const int y   = pix >> 8;
    const int x   = pix & 255;

    const float gx = (float)x - 127.5f;
    const float gy = (float)y - 127.5f;

    const float* __restrict__ sfb = g_sf + b * A_FULL * DET;

    float acc = 0.f;
    #pragma unroll 3
    for (int a = 0; a < A_FULL; a++) {
        const float t  = cs[a] * gx + sn[a] * gy + (float)(DET - 1) * 0.5f;
        const float t0 = floorf(t);
        const float w  = t - t0;
        int i = (int)t0;
        i = min(max(i, 0), DET - 2);            // safety clamp (never triggers)
        const float* row = sfb + a * DET;
        const float v0 = __ldg(row + i);
        const float v1 = __ldg(row + i + 1);
        acc += v0 + w * (v1 - v0);
    }
    out[p] = acc * (float)(CUDART_PI / (2.0 * A_FULL));
}

// ---------------------------------------------------------------------------
extern "C" void kernel_launch(void* const* d_in, const int* in_sizes, int n_in,
                              void* d_out, int out_size)
{
    const float* x_source = nullptr;
    const float* s_target = nullptr;
    const float* thetas   = nullptr;
    for (int i = 0; i < n_in; i++) {
        if      (in_sizes[i] == NB * IMG * IMG)   x_source = (const float*)d_in[i];
        else if (in_sizes[i] == NB * DET * N_ACQ) s_target = (const float*)d_in[i];
        else if (in_sizes[i] == A_FULL)           thetas   = (const float*)d_in[i];
    }

    transpose_kernel<<<dim3(IMG / 32, IMG / 32, NB), dim3(32, 8)>>>(x_source);
    radon_kernel    <<<dim3(A_FULL, NB, NCHUNK), 384>>>(x_source, thetas);
    filter_kernel   <<<dim3(A_FULL, NB), 384>>>(s_target);
    bp_kernel       <<<512, 256>>>((float*)d_out, thetas);
}

// round 3
// speedup vs baseline: 2.0845x; 1.0513x over previous
#include <cuda_runtime.h>
#include <math_constants.h>

#define IMG    256
#define DET    362          // int(256*sqrt(2)+0.5)
#define A_FULL 177          // (45-1)*4 + 1
#define N_ACQ  45
#define NB     2
#define NCHUNK 4
#define CHSZ   ((DET + NCHUNK - 1) / NCHUNK)   // 91

// Padded image geometry: 2-cell zero border (coords can reach index -2..257)
#define PW     264          // padded row stride (2 left + 256 + 6 right)
#define PH     260          // 2 top + 256 + 2 bottom
#define POFF   (2 * PW + 2) // offset of pixel (0,0)

// bp chunking
#define NCHBP  4
#define ABP    45           // ceil(177/4)

// Scratch (allocation-free)
__device__ float g_part[NCHUNK * NB * A_FULL * DET];  // radon partials
__device__ float g_sf  [NB * A_FULL * DET];           // filtered sinogram
__device__ float g_imP [NB * PH * PW];                // padded image
__device__ float g_imTP[NB * PH * PW];                // padded transposed image
__device__ float g_bp  [NCHBP * NB * IMG * IMG];      // backprojection partials

// ---------------------------------------------------------------------------
// Kernel 0: build zero-padded image + zero-padded transposed image.
// ---------------------------------------------------------------------------
__global__ void prep_kernel(const float* __restrict__ img)
{
    const int i = blockIdx.x * blockDim.x + threadIdx.x;
    if (i >= NB * PH * PW) return;
    const int b   = i / (PH * PW);
    const int rem = i - b * (PH * PW);
    const int r   = rem / PW;
    const int c   = rem - r * PW;
    const bool inter = (r >= 2) & (r < 2 + IMG) & (c >= 2) & (c < 2 + IMG);
    float v = 0.f, vt = 0.f;
    if (inter) {
        v  = __ldg(img + b * IMG * IMG + (r - 2) * IMG + (c - 2));
        vt = __ldg(img + b * IMG * IMG + (c - 2) * IMG + (r - 2));
    }
    g_imP [i] = v;
    g_imTP[i] = vt;
}

// ---------------------------------------------------------------------------
// Kernel 1: Radon transform, chunked over S, branch-free inner loop.
// grid = (A_FULL, NB, NCHUNK), block = 384 (one thread per detector bin t).
// Steep angles sample the transposed image with swapped coords (exact).
// Valid S-interval computed in closed form; padded image absorbs the
// +/-1-step fp slack, reproducing "invalid corners contribute 0" exactly.
// ---------------------------------------------------------------------------
__global__ void radon_kernel(const float* __restrict__ thetas_deg)
{
    const int a  = blockIdx.x;
    const int b  = blockIdx.y;
    const int ch = blockIdx.z;
    const int t  = threadIdx.x;
    if (t >= DET) return;

    const float th = thetas_deg[a] * (float)(CUDART_PI / 180.0);
    const float c  = cosf(th);
    const float s  = sinf(th);

    const float T  = (float)t - (float)(DET - 1) * 0.5f;
    const float bx = T * c + 127.5f;
    const float by = T * s + 127.5f;

    const bool swp = (s > fabsf(c));
    float q0, r0, dq, dr;
    const float* imc;
    if (swp) { q0 = by; r0 = bx; dq =  c; dr = -s; imc = g_imTP + b * PH * PW + POFF; }
    else     { q0 = bx; r0 = by; dq = -s; dr =  c; imc = g_imP  + b * PH * PW + POFF; }

    // Valid S interval: q0+S*dq in (-1,256) and r0+S*dr in (-1,256)
    float Slo = -1e9f, Shi = 1e9f;
    if (dq > 1e-6f)       { Slo = fmaxf(Slo, (-1.f - q0) / dq); Shi = fminf(Shi, (256.f - q0) / dq); }
    else if (dq < -1e-6f) { Slo = fmaxf(Slo, (256.f - q0) / dq); Shi = fminf(Shi, (-1.f - q0) / dq); }
    else if (q0 <= -1.f || q0 >= 256.f) Shi = -2e9f;
    if (dr > 1e-6f)       { Slo = fmaxf(Slo, (-1.f - r0) / dr); Shi = fminf(Shi, (256.f - r0) / dr); }
    else if (dr < -1e-6f) { Slo = fmaxf(Slo, (256.f - r0) / dr); Shi = fminf(Shi, (-1.f - r0) / dr); }
    else if (r0 <= -1.f || r0 >= 256.f) Shi = -2e9f;

    const float HALF = (float)(DET - 1) * 0.5f;   // 180.5
    int klo = (int)floorf(Slo + HALF);            // <=1 step outside: pad absorbs it
    int khi = (int)ceilf (Shi + HALF) + 1;        // exclusive
    klo = max(klo, ch * CHSZ);
    khi = min(khi, min(DET, (ch + 1) * CHSZ));

    float acc = 0.f;
    #pragma unroll 4
    for (int k = klo; k < khi; k++) {
        const float S  = (float)k - HALF;
        const float qs = fmaf(S, dq, q0);
        const float rs = fmaf(S, dr, r0);
        const float qf = floorf(qs), rf = floorf(rs);
        const float wq = qs - qf,    wr = rs - rf;
        const int   qi = (int)qf,    ri = (int)rf;

        const float* p = imc + ri * PW + qi;
        const float v00 = __ldg(p);
        const float v01 = __ldg(p + 1);
        const float v10 = __ldg(p + PW);
        const float v11 = __ldg(p + PW + 1);

        const float top = fmaf(wq, v01 - v00, v00);
        const float bot = fmaf(wq, v11 - v10, v10);
        acc = fmaf(wr, bot - top, acc + top);
    }

    g_part[((ch * NB + b) * A_FULL + a) * DET + t] = acc;
}

// ---------------------------------------------------------------------------
// Kernel 2: combine partials + data-consistency + exact ramp-filter conv.
//   h[0]=0.5, h[m odd]=-2/(pi m)^2, h[m even>0]=0 (exactly the FFT filter)
// ---------------------------------------------------------------------------
__global__ void filter_kernel(const float* __restrict__ s_target)
{
    __shared__ float xcol[DET];
    __shared__ float wtab[DET];

    const int a = blockIdx.x;
    const int b = blockIdx.y;
    const int d = threadIdx.x;

    for (int i = threadIdx.x; i < DET; i += blockDim.x) {
        float x = 0.f;
        #pragma unroll
        for (int ci = 0; ci < NCHUNK; ci++)
            x += g_part[((ci * NB + b) * A_FULL + a) * DET + i];
        if ((a & 3) == 0) {
            const int j = a >> 2;
            x = __ldg(s_target + (b * DET + i) * N_ACQ + j) - x;
        }
        xcol[i] = x;

        float wm;
        if (i == 0)      wm = 0.5f;
        else if (i & 1)  { const float fm = (float)i * (float)CUDART_PI; wm = -2.0f / (fm * fm); }
        else             wm = 0.f;
        wtab[i] = wm;
    }
    __syncthreads();

    if (d >= DET) return;

    float acc = 0.5f * xcol[d];
    const int k0 = (d & 1) ^ 1;           // opposite parity -> |d-k| odd
    #pragma unroll 4
    for (int k = k0; k < DET; k += 2) {
        const int m = abs(d - k);
        acc += wtab[m] * xcol[k];
    }
    g_sf[(b * A_FULL + a) * DET + d] = acc;
}

// ---------------------------------------------------------------------------
// Kernel 3: Filtered backprojection, chunked over angles for occupancy.
// grid = (512, NCHBP), block = 256. Partial per chunk -> g_bp.
// ---------------------------------------------------------------------------
__global__ void bp_kernel(const float* __restrict__ thetas_deg)
{
    __shared__ float cs[ABP];
    __shared__ float sn[ABP];

    const int ch  = blockIdx.y;
    const int a0  = ch * ABP;
    const int na  = min(A_FULL - a0, ABP);

    if (threadIdx.x < na) {
        const float th = thetas_deg[a0 + threadIdx.x] * (float)(CUDART_PI / 180.0);
        cs[threadIdx.x] = cosf(th);
        sn[threadIdx.x] = sinf(th);
    }
    __syncthreads();

    const int p   = blockIdx.x * blockDim.x + threadIdx.x;   // 0 .. 131071
    const int b   = p >> 16;
    const int pix = p & 65535;
    const int y   = pix >> 8;
    const int x   = pix & 255;

    const float gx = (float)x - 127.5f;
    const float gy = (float)y - 127.5f;

    const float* __restrict__ sfb = g_sf + b * A_FULL * DET + a0 * DET;

    float acc = 0.f;
    #pragma unroll 3
    for (int a = 0; a < na; a++) {
        const float t  = fmaf(cs[a], gx, fmaf(sn[a], gy, (float)(DET - 1) * 0.5f));
        const float t0 = floorf(t);
        const float w  = t - t0;
        int i = (int)t0;
        i = min(max(i, 0), DET - 2);            // safety clamp (never triggers)
        const float* row = sfb + a * DET;
        const float v0 = __ldg(row + i);
        const float v1 = __ldg(row + i + 1);
        acc = fmaf(w, v1 - v0, acc + v0);
    }
    g_bp[ch * (NB * IMG * IMG) + p] = acc;
}

// ---------------------------------------------------------------------------
// Kernel 4: reduce bp partials + scale.
// ---------------------------------------------------------------------------
__global__ void bp_reduce_kernel(float* __restrict__ out)
{
    const int p = blockIdx.x * blockDim.x + threadIdx.x;
    if (p >= NB * IMG * IMG) return;
    float acc = 0.f;
    #pragma unroll
    for (int ci = 0; ci < NCHBP; ci++)
        acc += g_bp[ci * (NB * IMG * IMG) + p];
    out[p] = acc * (float)(CUDART_PI / (2.0 * A_FULL));
}

// ---------------------------------------------------------------------------
extern "C" void kernel_launch(void* const* d_in, const int* in_sizes, int n_in,
                              void* d_out, int out_size)
{
    const float* x_source = nullptr;
    const float* s_target = nullptr;
    const float* thetas   = nullptr;
    for (int i = 0; i < n_in; i++) {
        if      (in_sizes[i] == NB * IMG * IMG)   x_source = (const float*)d_in[i];
        else if (in_sizes[i] == NB * DET * N_ACQ) s_target = (const float*)d_in[i];
        else if (in_sizes[i] == A_FULL)           thetas   = (const float*)d_in[i];
    }

    prep_kernel     <<<(NB * PH * PW + 255) / 256, 256>>>(x_source);
    radon_kernel    <<<dim3(A_FULL, NB, NCHUNK), 384>>>(thetas);
    filter_kernel   <<<dim3(A_FULL, NB), 384>>>(s_target);
    bp_kernel       <<<dim3(512, NCHBP), 256>>>(thetas);
    bp_reduce_kernel<<<512, 256>>>((float*)d_out);
}

// round 4
// speedup vs baseline: 2.4195x; 1.1607x over previous
#include <cuda_runtime.h>
#include <math_constants.h>

#define IMG    256
#define DET    362          // int(256*sqrt(2)+0.5)
#define A_FULL 177          // (45-1)*4 + 1
#define N_ACQ  45
#define NB     2
#define NCHUNK 4
#define CHSZ   ((DET + NCHUNK - 1) / NCHUNK)   // 91

// Padded image geometry: 2-cell zero border (coords can reach index -2..257)
#define PW     264          // padded row stride in ELEMENTS (float2)
#define PH     260          // 2 top + 256 + 2 bottom
#define POFF   (2 * PW + 2) // offset of pixel (0,0)

// bp chunking
#define NCHBP  4
#define ABP    45           // ceil(177/4)

// Scratch (allocation-free)
__device__ float  g_part[NCHUNK * NB * A_FULL * DET];  // radon partials
__device__ float2 g_sf2 [NB * A_FULL * DET];           // filtered sinogram, pair-packed
__device__ float2 g_imP2 [NB * PH * PW];               // padded image, pair-packed
__device__ float2 g_imTP2[NB * PH * PW];               // padded transposed image, pair-packed
__device__ float  g_bp  [NCHBP * NB * IMG * IMG];      // backprojection partials

// ---------------------------------------------------------------------------
// Kernel 0: build zero-padded pair-packed image + transposed image.
// P2[r][c] = (I[r][c], I[r][c+1]);  T2[r][c] = (I[c][r], I[c+1][r]).
// ---------------------------------------------------------------------------
__global__ void prep_kernel(const float* __restrict__ img)
{
    const int i = blockIdx.x * blockDim.x + threadIdx.x;
    if (i >= NB * PH * PW) return;
    const int b   = i / (PH * PW);
    const int rem = i - b * (PH * PW);
    const int r   = rem / PW - 2;     // image row  in [-2, PH-3]
    const int c   = rem - (r + 2) * PW - 2;  // image col in [-2, PW-3]
    const float* im = img + b * IMG * IMG;

    const bool rv = ((unsigned)r < IMG);
    const bool cv0 = ((unsigned)c < IMG);
    const bool cv1 = ((unsigned)(c + 1) < IMG);

    float2 v, vt;
    v.x  = (rv  && cv0) ? __ldg(im + r * IMG + c)       : 0.f;
    v.y  = (rv  && cv1) ? __ldg(im + r * IMG + c + 1)   : 0.f;
    vt.x = (cv0 && rv ) ? __ldg(im + c * IMG + r)       : 0.f;
    vt.y = (cv1 && rv ) ? __ldg(im + (c + 1) * IMG + r) : 0.f;
    g_imP2 [i] = v;
    g_imTP2[i] = vt;
}

// ---------------------------------------------------------------------------
// Kernel 1: Radon transform, chunked over S; 2x LDG.64 per bilinear sample.
// grid = (A_FULL, NB, NCHUNK), block = 384 (one thread per detector bin t).
// ---------------------------------------------------------------------------
__global__ void radon_kernel(const float* __restrict__ thetas_deg)
{
    const int a  = blockIdx.x;
    const int b  = blockIdx.y;
    const int ch = blockIdx.z;
    const int t  = threadIdx.x;
    if (t >= DET) return;

    const float th = thetas_deg[a] * (float)(CUDART_PI / 180.0);
    const float c  = cosf(th);
    const float s  = sinf(th);

    const float T  = (float)t - (float)(DET - 1) * 0.5f;
    const float bx = T * c + 127.5f;
    const float by = T * s + 127.5f;

    const bool swp = (s > fabsf(c));
    float q0, r0, dq, dr;
    const float2* imc;
    if (swp) { q0 = by; r0 = bx; dq =  c; dr = -s; imc = g_imTP2 + b * PH * PW + POFF; }
    else     { q0 = bx; r0 = by; dq = -s; dr =  c; imc = g_imP2  + b * PH * PW + POFF; }

    // Valid S interval: q0+S*dq in (-1,256) and r0+S*dr in (-1,256)
    float Slo = -1e9f, Shi = 1e9f;
    if (dq > 1e-6f)       { Slo = fmaxf(Slo, (-1.f - q0) / dq); Shi = fminf(Shi, (256.f - q0) / dq); }
    else if (dq < -1e-6f) { Slo = fmaxf(Slo, (256.f - q0) / dq); Shi = fminf(Shi, (-1.f - q0) / dq); }
    else if (q0 <= -1.f || q0 >= 256.f) Shi = -2e9f;
    if (dr > 1e-6f)       { Slo = fmaxf(Slo, (-1.f - r0) / dr); Shi = fminf(Shi, (256.f - r0) / dr); }
    else if (dr < -1e-6f) { Slo = fmaxf(Slo, (256.f - r0) / dr); Shi = fminf(Shi, (-1.f - r0) / dr); }
    else if (r0 <= -1.f || r0 >= 256.f) Shi = -2e9f;

    const float HALF = (float)(DET - 1) * 0.5f;   // 180.5
    int klo = (int)floorf(Slo + HALF);            // <=1 step outside: pad absorbs it
    int khi = (int)ceilf (Shi + HALF) + 1;        // exclusive
    klo = max(klo, ch * CHSZ);
    khi = min(khi, min(DET, (ch + 1) * CHSZ));

    float acc = 0.f;
    #pragma unroll 4
    for (int k = klo; k < khi; k++) {
        const float S  = (float)k - HALF;
        const float qs = fmaf(S, dq, q0);
        const float rs = fmaf(S, dr, r0);
        const float qf = floorf(qs), rf = floorf(rs);
        const float wq = qs - qf,    wr = rs - rf;
        const int   qi = (int)qf,    ri = (int)rf;

        const float2* p = imc + ri * PW + qi;
        const float2 a0 = __ldg(p);        // (v00, v01)
        const float2 a1 = __ldg(p + PW);   // (v10, v11)

        const float top = fmaf(wq, a0.y - a0.x, a0.x);
        const float bot = fmaf(wq, a1.y - a1.x, a1.x);
        acc = fmaf(wr, bot - top, acc + top);
    }

    g_part[((ch * NB + b) * A_FULL + a) * DET + t] = acc;
}

// ---------------------------------------------------------------------------
// Kernel 2: combine partials + data-consistency + exact ramp-filter conv,
// writing the pair-packed filtered sinogram.
//   h[0]=0.5, h[m odd]=-2/(pi m)^2, h[m even>0]=0 (exactly the FFT filter)
// ---------------------------------------------------------------------------
__global__ void filter_kernel(const float* __restrict__ s_target)
{
    __shared__ float xcol[DET];
    __shared__ float wtab[DET];
    __shared__ float res [DET];

    const int a = blockIdx.x;
    const int b = blockIdx.y;
    const int d = threadIdx.x;

    for (int i = threadIdx.x; i < DET; i += blockDim.x) {
        float x = 0.f;
        #pragma unroll
        for (int ci = 0; ci < NCHUNK; ci++)
            x += g_part[((ci * NB + b) * A_FULL + a) * DET + i];
        if ((a & 3) == 0) {
            const int j = a >> 2;
            x = __ldg(s_target + (b * DET + i) * N_ACQ + j) - x;
        }
        xcol[i] = x;

        float wm;
        if (i == 0)      wm = 0.5f;
        else if (i & 1)  { const float fm = (float)i * (float)CUDART_PI; wm = -2.0f / (fm * fm); }
        else             wm = 0.f;
        wtab[i] = wm;
    }
    __syncthreads();

    if (d < DET) {
        float acc = 0.5f * xcol[d];
        const int k0 = (d & 1) ^ 1;       // opposite parity -> |d-k| odd
        #pragma unroll 4
        for (int k = k0; k < DET; k += 2) {
            const int m = abs(d - k);
            acc += wtab[m] * xcol[k];
        }
        res[d] = acc;
    }
    __syncthreads();

    if (d < DET) {
        float2 o;
        o.x = res[d];
        o.y = (d + 1 < DET) ? res[d + 1] : 0.f;
        g_sf2[(b * A_FULL + a) * DET + d] = o;
    }
}

// ---------------------------------------------------------------------------
// Kernel 3: Filtered backprojection, chunked over angles; 1x LDG.64 / sample.
// grid = (512, NCHBP), block = 256.
// ---------------------------------------------------------------------------
__global__ void bp_kernel(const float* __restrict__ thetas_deg)
{
    __shared__ float cs[ABP];
    __shared__ float sn[ABP];

    const int ch  = blockIdx.y;
    const int a0  = ch * ABP;
    const int na  = min(A_FULL - a0, ABP);

    if (threadIdx.x < na) {
        const float th = thetas_deg[a0 + threadIdx.x] * (float)(CUDART_PI / 180.0);
        cs[threadIdx.x] = cosf(th);
        sn[threadIdx.x] = sinf(th);
    }
    __syncthreads();

    const int p   = blockIdx.x * blockDim.x + threadIdx.x;   // 0 .. 131071
    const int b   = p >> 16;
    const int pix = p & 65535;
    const int y   = pix >> 8;
    const int x   = pix & 255;

    const float gx = (float)x - 127.5f;
    const float gy = (float)y - 127.5f;

    const float2* __restrict__ sfb = g_sf2 + (b * A_FULL + a0) * DET;

    float acc = 0.f;
    #pragma unroll 3
    for (int a = 0; a < na; a++) {
        const float t  = fmaf(cs[a], gx, fmaf(sn[a], gy, (float)(DET - 1) * 0.5f));
        const float t0 = floorf(t);
        const float w  = t - t0;
        const int   i  = (int)t0;           // always in [0, 360]
        const float2 v = __ldg(sfb + a * DET + i);
        acc = fmaf(w, v.y - v.x, acc + v.x);
    }
    g_bp[ch * (NB * IMG * IMG) + p] = acc;
}

// ---------------------------------------------------------------------------
// Kernel 4: reduce bp partials + scale.
// ---------------------------------------------------------------------------
__global__ void bp_reduce_kernel(float* __restrict__ out)
{
    const int p = blockIdx.x * blockDim.x + threadIdx.x;
    if (p >= NB * IMG * IMG) return;
    float acc = 0.f;
    #pragma unroll
    for (int ci = 0; ci < NCHBP; ci++)
        acc += g_bp[ci * (NB * IMG * IMG) + p];
    out[p] = acc * (float)(CUDART_PI / (2.0 * A_FULL));
}

// ---------------------------------------------------------------------------
extern "C" void kernel_launch(void* const* d_in, const int* in_sizes, int n_in,
                              void* d_out, int out_size)
{
    const float* x_source = nullptr;
    const float* s_target = nullptr;
    const float* thetas   = nullptr;
    for (int i = 0; i < n_in; i++) {
        if      (in_sizes[i] == NB * IMG * IMG)   x_source = (const float*)d_in[i];
        else if (in_sizes[i] == NB * DET * N_ACQ) s_target = (const float*)d_in[i];
        else if (in_sizes[i] == A_FULL)           thetas   = (const float*)d_in[i];
    }

    prep_kernel     <<<(NB * PH * PW + 255) / 256, 256>>>(x_source);
    radon_kernel    <<<dim3(A_FULL, NB, NCHUNK), 384>>>(thetas);
    filter_kernel   <<<dim3(A_FULL, NB), 384>>>(s_target);
    bp_kernel       <<<dim3(512, NCHBP), 256>>>(thetas);
    bp_reduce_kernel<<<512, 256>>>((float*)d_out);
}

// round 5
// speedup vs baseline: 2.5162x; 1.0400x over previous
#include <cuda_runtime.h>
#include <math_constants.h>

#define IMG    256
#define DET    362          // int(256*sqrt(2)+0.5)
#define A_FULL 177          // (45-1)*4 + 1
#define N_ACQ  45
#define NB     2
#define NCHUNK 4
#define CHSZ   ((DET + NCHUNK - 1) / NCHUNK)   // 91

// Padded image geometry: 2-cell zero border (coords can reach index -2..257)
#define PW     264          // padded row stride in ELEMENTS (float2)
#define PH     260          // 2 top + 256 + 2 bottom
#define POFF   (2 * PW + 2) // offset of pixel (0,0)

// bp chunking
#define NCHBP  4
#define ABP    45           // ceil(177/4)

// Scratch (allocation-free)
__device__ float  g_part[NCHUNK * NB * A_FULL * DET];  // radon partials
__device__ float2 g_sf2 [NB * A_FULL * DET];           // filtered sinogram, pair-packed
__device__ float2 g_imP2 [NB * PH * PW];               // padded image, pair-packed
__device__ float2 g_imTP2[NB * PH * PW];               // padded transposed image, pair-packed
__device__ float  g_bp  [NCHBP * NB * IMG * IMG];      // backprojection partials

// ---------------------------------------------------------------------------
// Kernel 0: build zero-padded pair-packed image + transposed image.
// P2[r][c] = (I[r][c], I[r][c+1]);  T2[r][c] = (I[c][r], I[c+1][r]).
// ---------------------------------------------------------------------------
__global__ void prep_kernel(const float* __restrict__ img)
{
    const int i = blockIdx.x * blockDim.x + threadIdx.x;
    if (i >= NB * PH * PW) return;
    const int b   = i / (PH * PW);
    const int rem = i - b * (PH * PW);
    const int r   = rem / PW - 2;     // image row  in [-2, PH-3]
    const int c   = rem - (r + 2) * PW - 2;  // image col in [-2, PW-3]
    const float* im = img + b * IMG * IMG;

    const bool rv = ((unsigned)r < IMG);
    const bool cv0 = ((unsigned)c < IMG);
    const bool cv1 = ((unsigned)(c + 1) < IMG);

    float2 v, vt;
    v.x  = (rv  && cv0) ? __ldg(im + r * IMG + c)       : 0.f;
    v.y  = (rv  && cv1) ? __ldg(im + r * IMG + c + 1)   : 0.f;
    vt.x = (cv0 && rv ) ? __ldg(im + c * IMG + r)       : 0.f;
    vt.y = (cv1 && rv ) ? __ldg(im + (c + 1) * IMG + r) : 0.f;
    g_imP2 [i] = v;
    g_imTP2[i] = vt;
}

// ---------------------------------------------------------------------------
// Kernel 1: Radon transform, chunked over S; 2x LDG.64 per bilinear sample.
// grid = (A_FULL, NB, NCHUNK), block = 384 (one thread per detector bin t).
// ---------------------------------------------------------------------------
__global__ void radon_kernel(const float* __restrict__ thetas_deg)
{
    const int a  = blockIdx.x;
    const int b  = blockIdx.y;
    const int ch = blockIdx.z;
    const int t  = threadIdx.x;
    if (t >= DET) return;

    const float th = thetas_deg[a] * (float)(CUDART_PI / 180.0);
    const float c  = cosf(th);
    const float s  = sinf(th);

    const float T  = (float)t - (float)(DET - 1) * 0.5f;
    const float bx = T * c + 127.5f;
    const float by = T * s + 127.5f;

    const bool swp = (s > fabsf(c));
    float q0, r0, dq, dr;
    const float2* imc;
    if (swp) { q0 = by; r0 = bx; dq =  c; dr = -s; imc = g_imTP2 + b * PH * PW + POFF; }
    else     { q0 = bx; r0 = by; dq = -s; dr =  c; imc = g_imP2  + b * PH * PW + POFF; }

    // Valid S interval: q0+S*dq in (-1,256) and r0+S*dr in (-1,256)
    float Slo = -1e9f, Shi = 1e9f;
    if (dq > 1e-6f)       { Slo = fmaxf(Slo, (-1.f - q0) / dq); Shi = fminf(Shi, (256.f - q0) / dq); }
    else if (dq < -1e-6f) { Slo = fmaxf(Slo, (256.f - q0) / dq); Shi = fminf(Shi, (-1.f - q0) / dq); }
    else if (q0 <= -1.f || q0 >= 256.f) Shi = -2e9f;
    if (dr > 1e-6f)       { Slo = fmaxf(Slo, (-1.f - r0) / dr); Shi = fminf(Shi, (256.f - r0) / dr); }
    else if (dr < -1e-6f) { Slo = fmaxf(Slo, (256.f - r0) / dr); Shi = fminf(Shi, (-1.f - r0) / dr); }
    else if (r0 <= -1.f || r0 >= 256.f) Shi = -2e9f;

    const float HALF = (float)(DET - 1) * 0.5f;   // 180.5
    int klo = (int)floorf(Slo + HALF);            // <=1 step outside: pad absorbs it
    int khi = (int)ceilf (Shi + HALF) + 1;        // exclusive
    klo = max(klo, ch * CHSZ);
    khi = min(khi, min(DET, (ch + 1) * CHSZ));

    float acc = 0.f;
    #pragma unroll 4
    for (int k = klo; k < khi; k++) {
        const float S  = (float)k - HALF;
        const float qs = fmaf(S, dq, q0);
        const float rs = fmaf(S, dr, r0);
        const float qf = floorf(qs), rf = floorf(rs);
        const float wq = qs - qf,    wr = rs - rf;
        const int   qi = (int)qf,    ri = (int)rf;

        const float2* p = imc + ri * PW + qi;
        const float2 a0 = __ldg(p);        // (v00, v01)
        const float2 a1 = __ldg(p + PW);   // (v10, v11)

        const float top = fmaf(wq, a0.y - a0.x, a0.x);
        const float bot = fmaf(wq, a1.y - a1.x, a1.x);
        acc = fmaf(wr, bot - top, acc + top);
    }

    g_part[((ch * NB + b) * A_FULL + a) * DET + t] = acc;
}

// ---------------------------------------------------------------------------
// Kernel 2: combine partials + data-consistency + exact ramp-filter conv,
// writing the pair-packed filtered sinogram.
//   h[0]=0.5, h[m odd]=-2/(pi m)^2, h[m even>0]=0 (exactly the FFT filter)
// ---------------------------------------------------------------------------
__global__ void filter_kernel(const float* __restrict__ s_target)
{
    __shared__ float xcol[DET];
    __shared__ float wtab[DET];
    __shared__ float res [DET];

    const int a = blockIdx.x;
    const int b = blockIdx.y;
    const int d = threadIdx.x;

    for (int i = threadIdx.x; i < DET; i += blockDim.x) {
        float x = 0.f;
        #pragma unroll
        for (int ci = 0; ci < NCHUNK; ci++)
            x += g_part[((ci * NB + b) * A_FULL + a) * DET + i];
        if ((a & 3) == 0) {
            const int j = a >> 2;
            x = __ldg(s_target + (b * DET + i) * N_ACQ + j) - x;
        }
        xcol[i] = x;

        float wm;
        if (i == 0)      wm = 0.5f;
        else if (i & 1)  { const float fm = (float)i * (float)CUDART_PI; wm = -2.0f / (fm * fm); }
        else             wm = 0.f;
        wtab[i] = wm;
    }
    __syncthreads();

    if (d < DET) {
        float acc = 0.5f * xcol[d];
        const int k0 = (d & 1) ^ 1;       // opposite parity -> |d-k| odd
        #pragma unroll 4
        for (int k = k0; k < DET; k += 2) {
            const int m = abs(d - k);
            acc += wtab[m] * xcol[k];
        }
        res[d] = acc;
    }
    __syncthreads();

    if (d < DET) {
        float2 o;
        o.x = res[d];
        o.y = (d + 1 < DET) ? res[d + 1] : 0.f;
        g_sf2[(b * A_FULL + a) * DET + d] = o;
    }
}

// ---------------------------------------------------------------------------
// Kernel 3: Filtered backprojection, chunked over angles; 1x LDG.64 / sample.
// grid = (512, NCHBP), block = 256.
// ---------------------------------------------------------------------------
__global__ void bp_kernel(const float* __restrict__ thetas_deg)
{
    __shared__ float cs[ABP];
    __shared__ float sn[ABP];

    const int ch  = blockIdx.y;
    const int a0  = ch * ABP;
    const int na  = min(A_FULL - a0, ABP);

    if (threadIdx.x < na) {
        const float th = thetas_deg[a0 + threadIdx.x] * (float)(CUDART_PI / 180.0);
        cs[threadIdx.x] = cosf(th);
        sn[threadIdx.x] = sinf(th);
    }
    __syncthreads();

    const int p   = blockIdx.x * blockDim.x + threadIdx.x;   // 0 .. 131071
    const int b   = p >> 16;
    const int pix = p & 65535;
    const int y   = pix >> 8;
    const int x   = pix & 255;

    const float gx = (float)x - 127.5f;
    const float gy = (float)y - 127.5f;

    const float2* __restrict__ sfb = g_sf2 + (b * A_FULL + a0) * DET;

    float acc = 0.f;
    #pragma unroll 3
    for (int a = 0; a < na; a++) {
        const float t  = fmaf(cs[a], gx, fmaf(sn[a], gy, (float)(DET - 1) * 0.5f));
        const float t0 = floorf(t);
        const float w  = t - t0;
        const int   i  = (int)t0;           // always in [0, 360]
        const float2 v = __ldg(sfb + a * DET + i);
        acc = fmaf(w, v.y - v.x, acc + v.x);
    }
    g_bp[ch * (NB * IMG * IMG) + p] = acc;
}

// ---------------------------------------------------------------------------
// Kernel 4: reduce bp partials + scale.
// ---------------------------------------------------------------------------
__global__ void bp_reduce_kernel(float* __restrict__ out)
{
    const int p = blockIdx.x * blockDim.x + threadIdx.x;
    if (p >= NB * IMG * IMG) return;
    float acc = 0.f;
    #pragma unroll
    for (int ci = 0; ci < NCHBP; ci++)
        acc += g_bp[ci * (NB * IMG * IMG) + p];
    out[p] = acc * (float)(CUDART_PI / (2.0 * A_FULL));
}

// ---------------------------------------------------------------------------
extern "C" void kernel_launch(void* const* d_in, const int* in_sizes, int n_in,
                              void* d_out, int out_size)
{
    const float* x_source = nullptr;
    const float* s_target = nullptr;
    const float* thetas   = nullptr;
    for (int i = 0; i < n_in; i++) {
        if      (in_sizes[i] == NB * IMG * IMG)   x_source = (const float*)d_in[i];
        else if (in_sizes[i] == NB * DET * N_ACQ) s_target = (const float*)d_in[i];
        else if (in_sizes[i] == A_FULL)           thetas   = (const float*)d_in[i];
    }

    prep_kernel     <<<(NB * PH * PW + 255) / 256, 256>>>(x_source);
    radon_kernel    <<<dim3(A_FULL, NB, NCHUNK), 384>>>(thetas);
    filter_kernel   <<<dim3(A_FULL, NB), 384>>>(s_target);
    bp_kernel       <<<dim3(512, NCHBP), 256>>>(thetas);
    bp_reduce_kernel<<<512, 256>>>((float*)d_out);
}